// round 9
// baseline (speedup 1.0000x reference)
#include <cuda_runtime.h>
#include <cuda_bf16.h>
#include <cstdint>

// ---------------------------------------------------------------------------
// TwoLayerGCN on GB300 — round 8: two-stream graph fork (CSR build || GEMM prep
// + layer-1 GEMM), on top of the R7 mma.sync bf16-split pipeline.
//
//   deg[n]  = 1 + sum_{e: dst[e]==n} ew[e];  dinv = rsqrt(deg)
//   h       = x @ W                       (HMMA, bf16 hi/lo 3-term split)
//   out[d]  = dinv[d]*sum_e (w_e*dinv[s_e]) h[s_e] + dinv[d]^2 h[d] + b
// ---------------------------------------------------------------------------

#define MAX_NODES 50000
#define MAX_EDGES 1600000
#define F1 128
#define F2 64
#define K1DIM 256
#define SCAN_CHUNK 256
#define NUM_CHUNKS ((MAX_NODES + SCAN_CHUNK - 1) / SCAN_CHUNK)

__device__ int   g_count [MAX_NODES];
__device__ float g_deg   [MAX_NODES];
__device__ int   g_row   [MAX_NODES + 1];
__device__ int   g_cursor[MAX_NODES];
__device__ int   g_bsum  [NUM_CHUNKS];
__device__ int   g_bpre  [NUM_CHUNKS];
__device__ int2  g_edge  [MAX_EDGES];       // (src, w*dinv[src]) sorted by dst
__device__ float g_dinv  [MAX_NODES];
__device__ float g_h1    [MAX_NODES * F1];
__device__ float g_h2    [MAX_NODES * F2];
__device__ __nv_bfloat16 g_xhi [MAX_NODES * K1DIM];
__device__ __nv_bfloat16 g_xlo [MAX_NODES * K1DIM];
__device__ __nv_bfloat16 g_x2hi[MAX_NODES * F1];
__device__ __nv_bfloat16 g_x2lo[MAX_NODES * F1];
__device__ __nv_bfloat16 g_w1hi[F1 * K1DIM];   // W1^T [N=128, K=256]
__device__ __nv_bfloat16 g_w1lo[F1 * K1DIM];
__device__ __nv_bfloat16 g_w2hi[F2 * F1];      // W2^T [N=64, K=128]
__device__ __nv_bfloat16 g_w2lo[F2 * F1];
__device__ int   g_i64;

// ---------------- dtype detect / CSR build --------------------------------
__device__ __forceinline__ int load_idx(const void* ei, long long pos, int i64) {
    if (i64) return (int)((const long long*)ei)[pos];
    return ((const int*)ei)[pos];
}

__global__ void k_detect(const int* __restrict__ ei32) {
    __shared__ int nonzero;
    if (threadIdx.x == 0) nonzero = 0;
    __syncthreads();
    if (ei32[threadIdx.x * 2 + 1] != 0) atomicOr(&nonzero, 1);
    __syncthreads();
    if (threadIdx.x == 0) g_i64 = (nonzero == 0) ? 1 : 0;
}

__global__ void k_zero(int M) {
    int i = blockIdx.x * blockDim.x + threadIdx.x;
    if (i < M) { g_count[i] = 0; g_deg[i] = 1.0f; }
}

__global__ void k_histdeg(const void* __restrict__ ei,
                          const float* __restrict__ ew, int E) {
    int e = blockIdx.x * blockDim.x + threadIdx.x;
    if (e >= E) return;
    int d = load_idx(ei, (long long)E + e, g_i64);
    atomicAdd(&g_count[d], 1);
    atomicAdd(&g_deg[d], ew[e]);
}

__global__ void k_partial(int M) {
    __shared__ int wsum[8];
    int i = blockIdx.x * SCAN_CHUNK + threadIdx.x;
    int lane = threadIdx.x & 31, wid = threadIdx.x >> 5;
    int v = (i < M) ? g_count[i] : 0;
    #pragma unroll
    for (int off = 16; off > 0; off >>= 1)
        v += __shfl_xor_sync(0xffffffffu, v, off);
    if (lane == 0) wsum[wid] = v;
    __syncthreads();
    if (threadIdx.x == 0) {
        int s = 0;
        #pragma unroll
        for (int w = 0; w < 8; w++) s += wsum[w];
        g_bsum[blockIdx.x] = s;
    }
}

__global__ void k_scanb(int NB) {
    __shared__ int wpre[8];
    int tid = threadIdx.x, lane = tid & 31, wid = tid >> 5;
    int v = (tid < NB) ? g_bsum[tid] : 0;
    int inc = v;
    #pragma unroll
    for (int off = 1; off < 32; off <<= 1) {
        int t = __shfl_up_sync(0xffffffffu, inc, off);
        if (lane >= off) inc += t;
    }
    if (lane == 31) wpre[wid] = inc;
    __syncthreads();
    if (wid == 0) {
        int w = (lane < 8) ? wpre[lane] : 0;
        #pragma unroll
        for (int off = 1; off < 8; off <<= 1) {
            int t = __shfl_up_sync(0xffffffffu, w, off);
            if (lane >= off) w += t;
        }
        if (lane < 8) wpre[lane] = w;
    }
    __syncthreads();
    int excl = inc - v + (wid > 0 ? wpre[wid - 1] : 0);
    if (tid < NB) g_bpre[tid] = excl;
}

__global__ void k_write(int M) {
    __shared__ int wpre[8];
    int i = blockIdx.x * SCAN_CHUNK + threadIdx.x;
    int lane = threadIdx.x & 31, wid = threadIdx.x >> 5;
    int c = (i < M) ? g_count[i] : 0;
    int inc = c;
    #pragma unroll
    for (int off = 1; off < 32; off <<= 1) {
        int t = __shfl_up_sync(0xffffffffu, inc, off);
        if (lane >= off) inc += t;
    }
    if (lane == 31) wpre[wid] = inc;
    __syncthreads();
    if (wid == 0) {
        int w = (lane < 8) ? wpre[lane] : 0;
        #pragma unroll
        for (int off = 1; off < 8; off <<= 1) {
            int t = __shfl_up_sync(0xffffffffu, w, off);
            if (lane >= off) w += t;
        }
        if (lane < 8) wpre[lane] = w;
    }
    __syncthreads();
    int excl = inc - c + (wid > 0 ? wpre[wid - 1] : 0) + g_bpre[blockIdx.x];
    if (i < M) {
        g_row[i]    = excl;
        g_cursor[i] = excl;
        g_dinv[i]   = rsqrtf(g_deg[i]);
        if (i == M - 1) g_row[M] = excl + c;
    }
}

// fill sorted edges, folding dinv[src] into the weight
__global__ void k_fill(const void* __restrict__ ei,
                       const float* __restrict__ ew, int E) {
    int e = blockIdx.x * blockDim.x + threadIdx.x;
    if (e >= E) return;
    int i64 = g_i64;
    int s = load_idx(ei, e, i64);
    int d = load_idx(ei, (long long)E + e, i64);
    int pos = atomicAdd(&g_cursor[d], 1);
    g_edge[pos] = make_int2(s, __float_as_int(ew[e] * g_dinv[s]));
}

// ---------------- bf16 hi/lo split kernels ---------------------------------
__global__ void k_split(const float* __restrict__ x,
                        __nv_bfloat16* __restrict__ hi,
                        __nv_bfloat16* __restrict__ lo, long long n4) {
    long long i = (long long)blockIdx.x * blockDim.x + threadIdx.x;
    if (i >= n4) return;
    float4 v = *reinterpret_cast<const float4*>(x + i * 4);
    __nv_bfloat16 h0 = __float2bfloat16(v.x), h1 = __float2bfloat16(v.y);
    __nv_bfloat16 h2 = __float2bfloat16(v.z), h3 = __float2bfloat16(v.w);
    __nv_bfloat162 H0 = {h0, h1}, H1 = {h2, h3};
    __nv_bfloat162 L0 = {__float2bfloat16(v.x - __bfloat162float(h0)),
                         __float2bfloat16(v.y - __bfloat162float(h1))};
    __nv_bfloat162 L1 = {__float2bfloat16(v.z - __bfloat162float(h2)),
                         __float2bfloat16(v.w - __bfloat162float(h3))};
    *reinterpret_cast<__nv_bfloat162*>(hi + i * 4)     = H0;
    *reinterpret_cast<__nv_bfloat162*>(hi + i * 4 + 2) = H1;
    *reinterpret_cast<__nv_bfloat162*>(lo + i * 4)     = L0;
    *reinterpret_cast<__nv_bfloat162*>(lo + i * 4 + 2) = L1;
}

// W [K,N] fp32 -> W^T hi/lo [N,K] bf16
__global__ void k_prepW(const float* __restrict__ W,
                        __nv_bfloat16* __restrict__ Thi,
                        __nv_bfloat16* __restrict__ Tlo, int K, int N) {
    int i = blockIdx.x * blockDim.x + threadIdx.x;
    if (i >= K * N) return;
    int k = i / N, n = i % N;
    float v = W[i];
    __nv_bfloat16 h = __float2bfloat16(v);
    Thi[n * K + k] = h;
    Tlo[n * K + k] = __float2bfloat16(v - __bfloat162float(h));
}

// ---------------------------------------------------------------------------
// mma.sync bf16 split GEMM: C[M,N] = A @ B^T over 3 parts
//   part 0: A_hi x B_hi, part 1: A_lo x B_hi, part 2: A_hi x B_lo
// ---------------------------------------------------------------------------
template<int N, int K>
__global__ void __launch_bounds__(256, 2) k_gemm_mma(
    const __nv_bfloat16* __restrict__ Ahi, const __nv_bfloat16* __restrict__ Alo,
    const __nv_bfloat16* __restrict__ Bhi, const __nv_bfloat16* __restrict__ Blo,
    float* __restrict__ C, int M)
{
    constexpr int BK = 64;
    constexpr int SP = BK + 8;
    constexpr int NT = N / 16;

    __shared__ __nv_bfloat16 As[128][SP];
    __shared__ __nv_bfloat16 Bs[N][SP];

    const int tid  = threadIdx.x;
    const int wid  = tid >> 5, lane = tid & 31;
    const int wm   = wid & 3,  wn   = wid >> 2;
    const int row0 = blockIdx.x * 128;
    const int lr   = lane >> 2;
    const int lc   = lane & 3;

    float acc[2][NT][4] = {};

    for (int part = 0; part < 3; part++) {
        const __nv_bfloat16* A = (part == 1) ? Alo : Ahi;
        const __nv_bfloat16* B = (part == 2) ? Blo : Bhi;
        for (int k0 = 0; k0 < K; k0 += BK) {
            __syncthreads();
            #pragma unroll
            for (int i = tid; i < 128 * 8; i += 256) {
                int m = i >> 3, u = i & 7;
                int gm = row0 + m;
                uint4 v = make_uint4(0, 0, 0, 0);
                if (gm < M)
                    v = *reinterpret_cast<const uint4*>(A + (size_t)gm * K + k0 + u * 8);
                *reinterpret_cast<uint4*>(&As[m][u * 8]) = v;
            }
            #pragma unroll
            for (int i = tid; i < N * 8; i += 256) {
                int n = i >> 3, u = i & 7;
                uint4 v = *reinterpret_cast<const uint4*>(B + (size_t)n * K + k0 + u * 8);
                *reinterpret_cast<uint4*>(&Bs[n][u * 8]) = v;
            }
            __syncthreads();

            #pragma unroll
            for (int ks = 0; ks < BK / 16; ks++) {
                const int kw = ks * 8 + lc;
                uint32_t a[2][4];
                #pragma unroll
                for (int mt = 0; mt < 2; mt++) {
                    int r = wm * 32 + mt * 16 + lr;
                    const uint32_t* p0 = reinterpret_cast<const uint32_t*>(&As[r][0]);
                    const uint32_t* p8 = reinterpret_cast<const uint32_t*>(&As[r + 8][0]);
                    a[mt][0] = p0[kw];
                    a[mt][1] = p8[kw];
                    a[mt][2] = p0[kw + 4];
                    a[mt][3] = p8[kw + 4];
                }
                uint32_t b[NT][2];
                #pragma unroll
                for (int nt = 0; nt < NT; nt++) {
                    int n = wn * (N / 2) + nt * 8 + lr;
                    const uint32_t* pn = reinterpret_cast<const uint32_t*>(&Bs[n][0]);
                    b[nt][0] = pn[kw];
                    b[nt][1] = pn[kw + 4];
                }
                #pragma unroll
                for (int mt = 0; mt < 2; mt++)
                    #pragma unroll
                    for (int nt = 0; nt < NT; nt++) {
                        asm volatile(
                            "mma.sync.aligned.m16n8k16.row.col.f32.bf16.bf16.f32 "
                            "{%0,%1,%2,%3}, {%4,%5,%6,%7}, {%8,%9}, {%0,%1,%2,%3};"
                            : "+f"(acc[mt][nt][0]), "+f"(acc[mt][nt][1]),
                              "+f"(acc[mt][nt][2]), "+f"(acc[mt][nt][3])
                            : "r"(a[mt][0]), "r"(a[mt][1]), "r"(a[mt][2]), "r"(a[mt][3]),
                              "r"(b[nt][0]), "r"(b[nt][1]));
                    }
            }
        }
    }

    #pragma unroll
    for (int mt = 0; mt < 2; mt++) {
        int r  = row0 + wm * 32 + mt * 16 + lr;
        int r2 = r + 8;
        #pragma unroll
        for (int nt = 0; nt < NT; nt++) {
            int cb = wn * (N / 2) + nt * 8 + lc * 2;
            if (r < M)
                *reinterpret_cast<float2*>(C + (size_t)r  * N + cb) =
                    make_float2(acc[mt][nt][0], acc[mt][nt][1]);
            if (r2 < M)
                *reinterpret_cast<float2*>(C + (size_t)r2 * N + cb) =
                    make_float2(acc[mt][nt][2], acc[mt][nt][3]);
        }
    }
}

// ---------------------------------------------------------------------------
// aggregation: o[d] = act( dinv[d]*sum_e w'_e h[s] + dinv[d]^2 h[d] + bias )
// ---------------------------------------------------------------------------
template<int F, int VEC, bool RELU, bool SPLIT_OUT>
__global__ void k_agg(const float* __restrict__ h,
                      const float* __restrict__ bias,
                      float* __restrict__ out_f32,
                      __nv_bfloat16* __restrict__ out_hi,
                      __nv_bfloat16* __restrict__ out_lo, int M) {
    static_assert(F == 32 * VEC, "lane layout");
    int warp = (blockIdx.x * blockDim.x + threadIdx.x) >> 5;
    int lane = threadIdx.x & 31;
    if (warp >= M) return;

    const int r0 = g_row[warp], r1 = g_row[warp + 1];
    const int nfull = r0 + (((r1 - r0) >> 5) << 5);
    float acc[VEC] = {};

    for (int base = r0; base < nfull; base += 32) {
        int2 rec = g_edge[base + lane];
        #pragma unroll 4
        for (int j = 0; j < 32; j++) {
            int   sj = __shfl_sync(0xffffffffu, rec.x, j);
            float wj = __int_as_float(__shfl_sync(0xffffffffu, rec.y, j));
            const float* p = h + (size_t)sj * F + lane * VEC;
            if (VEC == 4) {
                float4 v = *reinterpret_cast<const float4*>(p);
                acc[0] += v.x * wj; acc[1] += v.y * wj;
                acc[2] += v.z * wj; acc[3] += v.w * wj;
            } else {
                float2 v = *reinterpret_cast<const float2*>(p);
                acc[0] += v.x * wj; acc[1] += v.y * wj;
            }
        }
    }
    {
        int n = r1 - nfull;
        int2 rec = make_int2(0, 0);
        if (lane < n) rec = g_edge[nfull + lane];
        for (int j = 0; j < n; j++) {
            int   sj = __shfl_sync(0xffffffffu, rec.x, j);
            float wj = __int_as_float(__shfl_sync(0xffffffffu, rec.y, j));
            const float* p = h + (size_t)sj * F + lane * VEC;
            if (VEC == 4) {
                float4 v = *reinterpret_cast<const float4*>(p);
                acc[0] += v.x * wj; acc[1] += v.y * wj;
                acc[2] += v.z * wj; acc[3] += v.w * wj;
            } else {
                float2 v = *reinterpret_cast<const float2*>(p);
                acc[0] += v.x * wj; acc[1] += v.y * wj;
            }
        }
    }

    const float* ps = h + (size_t)warp * F + lane * VEC;
    float di  = g_dinv[warp];
    float di2 = di * di;
    float r[VEC];
    #pragma unroll
    for (int k = 0; k < VEC; k++) {
        float o = di * acc[k] + di2 * ps[k] + bias[lane * VEC + k];
        r[k] = (RELU && o < 0.0f) ? 0.0f : o;
    }
    if (SPLIT_OUT) {
        __nv_bfloat16 hi[VEC], lo[VEC];
        #pragma unroll
        for (int k = 0; k < VEC; k++) {
            hi[k] = __float2bfloat16(r[k]);
            lo[k] = __float2bfloat16(r[k] - __bfloat162float(hi[k]));
        }
        __nv_bfloat16* ph = out_hi + (size_t)warp * F + lane * VEC;
        __nv_bfloat16* pl = out_lo + (size_t)warp * F + lane * VEC;
        #pragma unroll
        for (int k = 0; k < VEC; k += 2) {
            *reinterpret_cast<__nv_bfloat162*>(ph + k) = __nv_bfloat162{hi[k], hi[k + 1]};
            *reinterpret_cast<__nv_bfloat162*>(pl + k) = __nv_bfloat162{lo[k], lo[k + 1]};
        }
    } else {
        float* po = out_f32 + (size_t)warp * F + lane * VEC;
        if (VEC == 4) *reinterpret_cast<float4*>(po) = make_float4(r[0], r[1], r[2], r[3]);
        else          *reinterpret_cast<float2*>(po) = make_float2(r[0], r[1]);
    }
}

// ---------------------------------------------------------------------------
extern "C" void kernel_launch(void* const* d_in, const int* in_sizes, int n_in,
                              void* d_out, int out_size) {
    const float* x   = (const float*)d_in[0];
    const void*  ei  = d_in[1];
    const float* ew  = (const float*)d_in[2];
    const float* W1  = (const float*)d_in[3];
    const float* b1  = (const float*)d_in[4];
    const float* W2  = (const float*)d_in[5];
    const float* b2  = (const float*)d_in[6];
    float*       out = (float*)d_out;

    const int N1 = in_sizes[4];            // 128
    const int N2 = in_sizes[6];            // 64
    const int K1 = in_sizes[3] / N1;       // 256
    const int M  = in_sizes[0] / K1;       // 50000
    const int E  = in_sizes[2];            // 1600000
    const int NB = (M + SCAN_CHUNK - 1) / SCAN_CHUNK;

    float *p_h1, *p_h2;
    __nv_bfloat16 *p_xhi, *p_xlo, *p_x2hi, *p_x2lo, *p_w1hi, *p_w1lo, *p_w2hi, *p_w2lo;
    cudaGetSymbolAddress((void**)&p_h1,   g_h1);
    cudaGetSymbolAddress((void**)&p_h2,   g_h2);
    cudaGetSymbolAddress((void**)&p_xhi,  g_xhi);
    cudaGetSymbolAddress((void**)&p_xlo,  g_xlo);
    cudaGetSymbolAddress((void**)&p_x2hi, g_x2hi);
    cudaGetSymbolAddress((void**)&p_x2lo, g_x2lo);
    cudaGetSymbolAddress((void**)&p_w1hi, g_w1hi);
    cudaGetSymbolAddress((void**)&p_w1lo, g_w1lo);
    cudaGetSymbolAddress((void**)&p_w2hi, g_w2hi);
    cudaGetSymbolAddress((void**)&p_w2lo, g_w2lo);

    // Lazily-created side stream + fork/join events (host resources only;
    // identical device work every call). Fall back to stream 0 on failure.
    static cudaStream_t s2 = nullptr;
    static cudaEvent_t  evFork = nullptr, evJoin = nullptr;
    static bool         inited = false;
    if (!inited) {
        if (cudaStreamCreateWithFlags(&s2, cudaStreamNonBlocking) != cudaSuccess) s2 = nullptr;
        cudaEventCreateWithFlags(&evFork, cudaEventDisableTiming);
        cudaEventCreateWithFlags(&evJoin, cudaEventDisableTiming);
        inited = true;
    }
    cudaStream_t sB = s2 ? s2 : (cudaStream_t)0;
    const bool forked = (s2 != nullptr) && evFork && evJoin;

    // ---- fork ----
    if (forked) {
        cudaEventRecord(evFork, 0);
        cudaStreamWaitEvent(sB, evFork, 0);
    }

    // Stream B: GEMM-prep path (independent of CSR): split x, transpose W, gemm1
    {
        long long n4 = (long long)M * K1 / 4;
        k_split<<<(unsigned)((n4 + 255) / 256), 256, 0, sB>>>(x, p_xhi, p_xlo, n4);
    }
    k_prepW<<<(K1 * N1 + 255) / 256, 256, 0, sB>>>(W1, p_w1hi, p_w1lo, K1, N1);
    k_prepW<<<(N1 * N2 + 255) / 256, 256, 0, sB>>>(W2, p_w2hi, p_w2lo, N1, N2);
    k_gemm_mma<128, 256><<<(M + 127) / 128, 256, 0, sB>>>(p_xhi, p_xlo, p_w1hi, p_w1lo, p_h1, M);

    // Stream 0: CSR build
    k_detect <<<1, 256>>>((const int*)ei);
    k_zero   <<<(M + 255) / 256, 256>>>(M);
    k_histdeg<<<(E + 255) / 256, 256>>>(ei, ew, E);
    k_partial<<<NB, SCAN_CHUNK>>>(M);
    k_scanb  <<<1, 256>>>(NB);
    k_write  <<<NB, SCAN_CHUNK>>>(M);
    k_fill   <<<(E + 255) / 256, 256>>>(ei, ew, E);

    // ---- join ----
    if (forked) {
        cudaEventRecord(evJoin, sB);
        cudaStreamWaitEvent(0, evJoin, 0);
    }

    // layer 1 aggregate -> x2 (bf16 hi/lo)
    k_agg<F1, 4, true, true><<<(M * 32 + 255) / 256, 256>>>(p_h1, b1, nullptr, p_x2hi, p_x2lo, M);

    // layer 2: gemm + aggregate -> out
    k_gemm_mma<64, 128><<<(M + 127) / 128, 256>>>(p_x2hi, p_x2lo, p_w2hi, p_w2lo, p_h2, M);
    k_agg<F2, 2, false, false><<<(M * 32 + 255) / 256, 256>>>(p_h2, b2, out, nullptr, nullptr, M);
}

// round 10
// speedup vs baseline: 1.0034x; 1.0034x over previous
#include <cuda_runtime.h>
#include <cuda_bf16.h>
#include <cstdint>

// ---------------------------------------------------------------------------
// TwoLayerGCN on GB300 — round 8: two-stream graph fork (CSR build || GEMM prep
// + layer-1 GEMM), on top of the R7 mma.sync bf16-split pipeline.
//
//   deg[n]  = 1 + sum_{e: dst[e]==n} ew[e];  dinv = rsqrt(deg)
//   h       = x @ W                       (HMMA, bf16 hi/lo 3-term split)
//   out[d]  = dinv[d]*sum_e (w_e*dinv[s_e]) h[s_e] + dinv[d]^2 h[d] + b
// ---------------------------------------------------------------------------

#define MAX_NODES 50000
#define MAX_EDGES 1600000
#define F1 128
#define F2 64
#define K1DIM 256
#define SCAN_CHUNK 256
#define NUM_CHUNKS ((MAX_NODES + SCAN_CHUNK - 1) / SCAN_CHUNK)

__device__ int   g_count [MAX_NODES];
__device__ float g_deg   [MAX_NODES];
__device__ int   g_row   [MAX_NODES + 1];
__device__ int   g_cursor[MAX_NODES];
__device__ int   g_bsum  [NUM_CHUNKS];
__device__ int   g_bpre  [NUM_CHUNKS];
__device__ int2  g_edge  [MAX_EDGES];       // (src, w*dinv[src]) sorted by dst
__device__ float g_dinv  [MAX_NODES];
__device__ float g_h1    [MAX_NODES * F1];
__device__ float g_h2    [MAX_NODES * F2];
__device__ __nv_bfloat16 g_xhi [MAX_NODES * K1DIM];
__device__ __nv_bfloat16 g_xlo [MAX_NODES * K1DIM];
__device__ __nv_bfloat16 g_x2hi[MAX_NODES * F1];
__device__ __nv_bfloat16 g_x2lo[MAX_NODES * F1];
__device__ __nv_bfloat16 g_w1hi[F1 * K1DIM];   // W1^T [N=128, K=256]
__device__ __nv_bfloat16 g_w1lo[F1 * K1DIM];
__device__ __nv_bfloat16 g_w2hi[F2 * F1];      // W2^T [N=64, K=128]
__device__ __nv_bfloat16 g_w2lo[F2 * F1];
__device__ int   g_i64;

// ---------------- dtype detect / CSR build --------------------------------
__device__ __forceinline__ int load_idx(const void* ei, long long pos, int i64) {
    if (i64) return (int)((const long long*)ei)[pos];
    return ((const int*)ei)[pos];
}

__global__ void k_detect(const int* __restrict__ ei32) {
    __shared__ int nonzero;
    if (threadIdx.x == 0) nonzero = 0;
    __syncthreads();
    if (ei32[threadIdx.x * 2 + 1] != 0) atomicOr(&nonzero, 1);
    __syncthreads();
    if (threadIdx.x == 0) g_i64 = (nonzero == 0) ? 1 : 0;
}

__global__ void k_zero(int M) {
    int i = blockIdx.x * blockDim.x + threadIdx.x;
    if (i < M) { g_count[i] = 0; g_deg[i] = 1.0f; }
}

__global__ void k_histdeg(const void* __restrict__ ei,
                          const float* __restrict__ ew, int E) {
    int e = blockIdx.x * blockDim.x + threadIdx.x;
    if (e >= E) return;
    int d = load_idx(ei, (long long)E + e, g_i64);
    atomicAdd(&g_count[d], 1);
    atomicAdd(&g_deg[d], ew[e]);
}

__global__ void k_partial(int M) {
    __shared__ int wsum[8];
    int i = blockIdx.x * SCAN_CHUNK + threadIdx.x;
    int lane = threadIdx.x & 31, wid = threadIdx.x >> 5;
    int v = (i < M) ? g_count[i] : 0;
    #pragma unroll
    for (int off = 16; off > 0; off >>= 1)
        v += __shfl_xor_sync(0xffffffffu, v, off);
    if (lane == 0) wsum[wid] = v;
    __syncthreads();
    if (threadIdx.x == 0) {
        int s = 0;
        #pragma unroll
        for (int w = 0; w < 8; w++) s += wsum[w];
        g_bsum[blockIdx.x] = s;
    }
}

__global__ void k_scanb(int NB) {
    __shared__ int wpre[8];
    int tid = threadIdx.x, lane = tid & 31, wid = tid >> 5;
    int v = (tid < NB) ? g_bsum[tid] : 0;
    int inc = v;
    #pragma unroll
    for (int off = 1; off < 32; off <<= 1) {
        int t = __shfl_up_sync(0xffffffffu, inc, off);
        if (lane >= off) inc += t;
    }
    if (lane == 31) wpre[wid] = inc;
    __syncthreads();
    if (wid == 0) {
        int w = (lane < 8) ? wpre[lane] : 0;
        #pragma unroll
        for (int off = 1; off < 8; off <<= 1) {
            int t = __shfl_up_sync(0xffffffffu, w, off);
            if (lane >= off) w += t;
        }
        if (lane < 8) wpre[lane] = w;
    }
    __syncthreads();
    int excl = inc - v + (wid > 0 ? wpre[wid - 1] : 0);
    if (tid < NB) g_bpre[tid] = excl;
}

__global__ void k_write(int M) {
    __shared__ int wpre[8];
    int i = blockIdx.x * SCAN_CHUNK + threadIdx.x;
    int lane = threadIdx.x & 31, wid = threadIdx.x >> 5;
    int c = (i < M) ? g_count[i] : 0;
    int inc = c;
    #pragma unroll
    for (int off = 1; off < 32; off <<= 1) {
        int t = __shfl_up_sync(0xffffffffu, inc, off);
        if (lane >= off) inc += t;
    }
    if (lane == 31) wpre[wid] = inc;
    __syncthreads();
    if (wid == 0) {
        int w = (lane < 8) ? wpre[lane] : 0;
        #pragma unroll
        for (int off = 1; off < 8; off <<= 1) {
            int t = __shfl_up_sync(0xffffffffu, w, off);
            if (lane >= off) w += t;
        }
        if (lane < 8) wpre[lane] = w;
    }
    __syncthreads();
    int excl = inc - c + (wid > 0 ? wpre[wid - 1] : 0) + g_bpre[blockIdx.x];
    if (i < M) {
        g_row[i]    = excl;
        g_cursor[i] = excl;
        g_dinv[i]   = rsqrtf(g_deg[i]);
        if (i == M - 1) g_row[M] = excl + c;
    }
}

// fill sorted edges, folding dinv[src] into the weight
__global__ void k_fill(const void* __restrict__ ei,
                       const float* __restrict__ ew, int E) {
    int e = blockIdx.x * blockDim.x + threadIdx.x;
    if (e >= E) return;
    int i64 = g_i64;
    int s = load_idx(ei, e, i64);
    int d = load_idx(ei, (long long)E + e, i64);
    int pos = atomicAdd(&g_cursor[d], 1);
    g_edge[pos] = make_int2(s, __float_as_int(ew[e] * g_dinv[s]));
}

// ---------------- bf16 hi/lo split kernels ---------------------------------
__global__ void k_split(const float* __restrict__ x,
                        __nv_bfloat16* __restrict__ hi,
                        __nv_bfloat16* __restrict__ lo, long long n4) {
    long long i = (long long)blockIdx.x * blockDim.x + threadIdx.x;
    if (i >= n4) return;
    float4 v = *reinterpret_cast<const float4*>(x + i * 4);
    __nv_bfloat16 h0 = __float2bfloat16(v.x), h1 = __float2bfloat16(v.y);
    __nv_bfloat16 h2 = __float2bfloat16(v.z), h3 = __float2bfloat16(v.w);
    __nv_bfloat162 H0 = {h0, h1}, H1 = {h2, h3};
    __nv_bfloat162 L0 = {__float2bfloat16(v.x - __bfloat162float(h0)),
                         __float2bfloat16(v.y - __bfloat162float(h1))};
    __nv_bfloat162 L1 = {__float2bfloat16(v.z - __bfloat162float(h2)),
                         __float2bfloat16(v.w - __bfloat162float(h3))};
    *reinterpret_cast<__nv_bfloat162*>(hi + i * 4)     = H0;
    *reinterpret_cast<__nv_bfloat162*>(hi + i * 4 + 2) = H1;
    *reinterpret_cast<__nv_bfloat162*>(lo + i * 4)     = L0;
    *reinterpret_cast<__nv_bfloat162*>(lo + i * 4 + 2) = L1;
}

// W [K,N] fp32 -> W^T hi/lo [N,K] bf16
__global__ void k_prepW(const float* __restrict__ W,
                        __nv_bfloat16* __restrict__ Thi,
                        __nv_bfloat16* __restrict__ Tlo, int K, int N) {
    int i = blockIdx.x * blockDim.x + threadIdx.x;
    if (i >= K * N) return;
    int k = i / N, n = i % N;
    float v = W[i];
    __nv_bfloat16 h = __float2bfloat16(v);
    Thi[n * K + k] = h;
    Tlo[n * K + k] = __float2bfloat16(v - __bfloat162float(h));
}

// ---------------------------------------------------------------------------
// mma.sync bf16 split GEMM: C[M,N] = A @ B^T over 3 parts
//   part 0: A_hi x B_hi, part 1: A_lo x B_hi, part 2: A_hi x B_lo
// ---------------------------------------------------------------------------
template<int N, int K>
__global__ void __launch_bounds__(256, 2) k_gemm_mma(
    const __nv_bfloat16* __restrict__ Ahi, const __nv_bfloat16* __restrict__ Alo,
    const __nv_bfloat16* __restrict__ Bhi, const __nv_bfloat16* __restrict__ Blo,
    float* __restrict__ C, int M)
{
    constexpr int BK = 64;
    constexpr int SP = BK + 8;
    constexpr int NT = N / 16;

    __shared__ __nv_bfloat16 As[128][SP];
    __shared__ __nv_bfloat16 Bs[N][SP];

    const int tid  = threadIdx.x;
    const int wid  = tid >> 5, lane = tid & 31;
    const int wm   = wid & 3,  wn   = wid >> 2;
    const int row0 = blockIdx.x * 128;
    const int lr   = lane >> 2;
    const int lc   = lane & 3;

    float acc[2][NT][4] = {};

    for (int part = 0; part < 3; part++) {
        const __nv_bfloat16* A = (part == 1) ? Alo : Ahi;
        const __nv_bfloat16* B = (part == 2) ? Blo : Bhi;
        for (int k0 = 0; k0 < K; k0 += BK) {
            __syncthreads();
            #pragma unroll
            for (int i = tid; i < 128 * 8; i += 256) {
                int m = i >> 3, u = i & 7;
                int gm = row0 + m;
                uint4 v = make_uint4(0, 0, 0, 0);
                if (gm < M)
                    v = *reinterpret_cast<const uint4*>(A + (size_t)gm * K + k0 + u * 8);
                *reinterpret_cast<uint4*>(&As[m][u * 8]) = v;
            }
            #pragma unroll
            for (int i = tid; i < N * 8; i += 256) {
                int n = i >> 3, u = i & 7;
                uint4 v = *reinterpret_cast<const uint4*>(B + (size_t)n * K + k0 + u * 8);
                *reinterpret_cast<uint4*>(&Bs[n][u * 8]) = v;
            }
            __syncthreads();

            #pragma unroll
            for (int ks = 0; ks < BK / 16; ks++) {
                const int kw = ks * 8 + lc;
                uint32_t a[2][4];
                #pragma unroll
                for (int mt = 0; mt < 2; mt++) {
                    int r = wm * 32 + mt * 16 + lr;
                    const uint32_t* p0 = reinterpret_cast<const uint32_t*>(&As[r][0]);
                    const uint32_t* p8 = reinterpret_cast<const uint32_t*>(&As[r + 8][0]);
                    a[mt][0] = p0[kw];
                    a[mt][1] = p8[kw];
                    a[mt][2] = p0[kw + 4];
                    a[mt][3] = p8[kw + 4];
                }
                uint32_t b[NT][2];
                #pragma unroll
                for (int nt = 0; nt < NT; nt++) {
                    int n = wn * (N / 2) + nt * 8 + lr;
                    const uint32_t* pn = reinterpret_cast<const uint32_t*>(&Bs[n][0]);
                    b[nt][0] = pn[kw];
                    b[nt][1] = pn[kw + 4];
                }
                #pragma unroll
                for (int mt = 0; mt < 2; mt++)
                    #pragma unroll
                    for (int nt = 0; nt < NT; nt++) {
                        asm volatile(
                            "mma.sync.aligned.m16n8k16.row.col.f32.bf16.bf16.f32 "
                            "{%0,%1,%2,%3}, {%4,%5,%6,%7}, {%8,%9}, {%0,%1,%2,%3};"
                            : "+f"(acc[mt][nt][0]), "+f"(acc[mt][nt][1]),
                              "+f"(acc[mt][nt][2]), "+f"(acc[mt][nt][3])
                            : "r"(a[mt][0]), "r"(a[mt][1]), "r"(a[mt][2]), "r"(a[mt][3]),
                              "r"(b[nt][0]), "r"(b[nt][1]));
                    }
            }
        }
    }

    #pragma unroll
    for (int mt = 0; mt < 2; mt++) {
        int r  = row0 + wm * 32 + mt * 16 + lr;
        int r2 = r + 8;
        #pragma unroll
        for (int nt = 0; nt < NT; nt++) {
            int cb = wn * (N / 2) + nt * 8 + lc * 2;
            if (r < M)
                *reinterpret_cast<float2*>(C + (size_t)r  * N + cb) =
                    make_float2(acc[mt][nt][0], acc[mt][nt][1]);
            if (r2 < M)
                *reinterpret_cast<float2*>(C + (size_t)r2 * N + cb) =
                    make_float2(acc[mt][nt][2], acc[mt][nt][3]);
        }
    }
}

// ---------------------------------------------------------------------------
// aggregation: o[d] = act( dinv[d]*sum_e w'_e h[s] + dinv[d]^2 h[d] + bias )
// ---------------------------------------------------------------------------
template<int F, int VEC, bool RELU, bool SPLIT_OUT>
__global__ void k_agg(const float* __restrict__ h,
                      const float* __restrict__ bias,
                      float* __restrict__ out_f32,
                      __nv_bfloat16* __restrict__ out_hi,
                      __nv_bfloat16* __restrict__ out_lo, int M) {
    static_assert(F == 32 * VEC, "lane layout");
    int warp = (blockIdx.x * blockDim.x + threadIdx.x) >> 5;
    int lane = threadIdx.x & 31;
    if (warp >= M) return;

    const int r0 = g_row[warp], r1 = g_row[warp + 1];
    const int nfull = r0 + (((r1 - r0) >> 5) << 5);
    float acc[VEC] = {};

    for (int base = r0; base < nfull; base += 32) {
        int2 rec = g_edge[base + lane];
        #pragma unroll 4
        for (int j = 0; j < 32; j++) {
            int   sj = __shfl_sync(0xffffffffu, rec.x, j);
            float wj = __int_as_float(__shfl_sync(0xffffffffu, rec.y, j));
            const float* p = h + (size_t)sj * F + lane * VEC;
            if (VEC == 4) {
                float4 v = *reinterpret_cast<const float4*>(p);
                acc[0] += v.x * wj; acc[1] += v.y * wj;
                acc[2] += v.z * wj; acc[3] += v.w * wj;
            } else {
                float2 v = *reinterpret_cast<const float2*>(p);
                acc[0] += v.x * wj; acc[1] += v.y * wj;
            }
        }
    }
    {
        int n = r1 - nfull;
        int2 rec = make_int2(0, 0);
        if (lane < n) rec = g_edge[nfull + lane];
        for (int j = 0; j < n; j++) {
            int   sj = __shfl_sync(0xffffffffu, rec.x, j);
            float wj = __int_as_float(__shfl_sync(0xffffffffu, rec.y, j));
            const float* p = h + (size_t)sj * F + lane * VEC;
            if (VEC == 4) {
                float4 v = *reinterpret_cast<const float4*>(p);
                acc[0] += v.x * wj; acc[1] += v.y * wj;
                acc[2] += v.z * wj; acc[3] += v.w * wj;
            } else {
                float2 v = *reinterpret_cast<const float2*>(p);
                acc[0] += v.x * wj; acc[1] += v.y * wj;
            }
        }
    }

    const float* ps = h + (size_t)warp * F + lane * VEC;
    float di  = g_dinv[warp];
    float di2 = di * di;
    float r[VEC];
    #pragma unroll
    for (int k = 0; k < VEC; k++) {
        float o = di * acc[k] + di2 * ps[k] + bias[lane * VEC + k];
        r[k] = (RELU && o < 0.0f) ? 0.0f : o;
    }
    if (SPLIT_OUT) {
        __nv_bfloat16 hi[VEC], lo[VEC];
        #pragma unroll
        for (int k = 0; k < VEC; k++) {
            hi[k] = __float2bfloat16(r[k]);
            lo[k] = __float2bfloat16(r[k] - __bfloat162float(hi[k]));
        }
        __nv_bfloat16* ph = out_hi + (size_t)warp * F + lane * VEC;
        __nv_bfloat16* pl = out_lo + (size_t)warp * F + lane * VEC;
        #pragma unroll
        for (int k = 0; k < VEC; k += 2) {
            *reinterpret_cast<__nv_bfloat162*>(ph + k) = __nv_bfloat162{hi[k], hi[k + 1]};
            *reinterpret_cast<__nv_bfloat162*>(pl + k) = __nv_bfloat162{lo[k], lo[k + 1]};
        }
    } else {
        float* po = out_f32 + (size_t)warp * F + lane * VEC;
        if (VEC == 4) *reinterpret_cast<float4*>(po) = make_float4(r[0], r[1], r[2], r[3]);
        else          *reinterpret_cast<float2*>(po) = make_float2(r[0], r[1]);
    }
}

// ---------------------------------------------------------------------------
extern "C" void kernel_launch(void* const* d_in, const int* in_sizes, int n_in,
                              void* d_out, int out_size) {
    const float* x   = (const float*)d_in[0];
    const void*  ei  = d_in[1];
    const float* ew  = (const float*)d_in[2];
    const float* W1  = (const float*)d_in[3];
    const float* b1  = (const float*)d_in[4];
    const float* W2  = (const float*)d_in[5];
    const float* b2  = (const float*)d_in[6];
    float*       out = (float*)d_out;

    const int N1 = in_sizes[4];            // 128
    const int N2 = in_sizes[6];            // 64
    const int K1 = in_sizes[3] / N1;       // 256
    const int M  = in_sizes[0] / K1;       // 50000
    const int E  = in_sizes[2];            // 1600000
    const int NB = (M + SCAN_CHUNK - 1) / SCAN_CHUNK;

    float *p_h1, *p_h2;
    __nv_bfloat16 *p_xhi, *p_xlo, *p_x2hi, *p_x2lo, *p_w1hi, *p_w1lo, *p_w2hi, *p_w2lo;
    cudaGetSymbolAddress((void**)&p_h1,   g_h1);
    cudaGetSymbolAddress((void**)&p_h2,   g_h2);
    cudaGetSymbolAddress((void**)&p_xhi,  g_xhi);
    cudaGetSymbolAddress((void**)&p_xlo,  g_xlo);
    cudaGetSymbolAddress((void**)&p_x2hi, g_x2hi);
    cudaGetSymbolAddress((void**)&p_x2lo, g_x2lo);
    cudaGetSymbolAddress((void**)&p_w1hi, g_w1hi);
    cudaGetSymbolAddress((void**)&p_w1lo, g_w1lo);
    cudaGetSymbolAddress((void**)&p_w2hi, g_w2hi);
    cudaGetSymbolAddress((void**)&p_w2lo, g_w2lo);

    // Lazily-created side stream + fork/join events (host resources only;
    // identical device work every call). Fall back to stream 0 on failure.
    static cudaStream_t s2 = nullptr;
    static cudaEvent_t  evFork = nullptr, evJoin = nullptr;
    static bool         inited = false;
    if (!inited) {
        if (cudaStreamCreateWithFlags(&s2, cudaStreamNonBlocking) != cudaSuccess) s2 = nullptr;
        cudaEventCreateWithFlags(&evFork, cudaEventDisableTiming);
        cudaEventCreateWithFlags(&evJoin, cudaEventDisableTiming);
        inited = true;
    }
    cudaStream_t sB = s2 ? s2 : (cudaStream_t)0;
    const bool forked = (s2 != nullptr) && evFork && evJoin;

    // ---- fork ----
    if (forked) {
        cudaEventRecord(evFork, 0);
        cudaStreamWaitEvent(sB, evFork, 0);
    }

    // Stream B: GEMM-prep path (independent of CSR): split x, transpose W, gemm1
    {
        long long n4 = (long long)M * K1 / 4;
        k_split<<<(unsigned)((n4 + 255) / 256), 256, 0, sB>>>(x, p_xhi, p_xlo, n4);
    }
    k_prepW<<<(K1 * N1 + 255) / 256, 256, 0, sB>>>(W1, p_w1hi, p_w1lo, K1, N1);
    k_prepW<<<(N1 * N2 + 255) / 256, 256, 0, sB>>>(W2, p_w2hi, p_w2lo, N1, N2);
    k_gemm_mma<128, 256><<<(M + 127) / 128, 256, 0, sB>>>(p_xhi, p_xlo, p_w1hi, p_w1lo, p_h1, M);

    // Stream 0: CSR build
    k_detect <<<1, 256>>>((const int*)ei);
    k_zero   <<<(M + 255) / 256, 256>>>(M);
    k_histdeg<<<(E + 255) / 256, 256>>>(ei, ew, E);
    k_partial<<<NB, SCAN_CHUNK>>>(M);
    k_scanb  <<<1, 256>>>(NB);
    k_write  <<<NB, SCAN_CHUNK>>>(M);
    k_fill   <<<(E + 255) / 256, 256>>>(ei, ew, E);

    // ---- join ----
    if (forked) {
        cudaEventRecord(evJoin, sB);
        cudaStreamWaitEvent(0, evJoin, 0);
    }

    // layer 1 aggregate -> x2 (bf16 hi/lo)
    k_agg<F1, 4, true, true><<<(M * 32 + 255) / 256, 256>>>(p_h1, b1, nullptr, p_x2hi, p_x2lo, M);

    // layer 2: gemm + aggregate -> out
    k_gemm_mma<64, 128><<<(M + 127) / 128, 256>>>(p_x2hi, p_x2lo, p_w2hi, p_w2lo, p_h2, M);
    k_agg<F2, 2, false, false><<<(M * 32 + 255) / 256, 256>>>(p_h2, b2, out, nullptr, nullptr, M);
}

// round 11
// speedup vs baseline: 1.1409x; 1.1370x over previous
#include <cuda_runtime.h>
#include <cuda_bf16.h>
#include <cstdint>

// ---------------------------------------------------------------------------
// TwoLayerGCN on GB300 — round 11: ldmatrix + shared-fragment split GEMM
// (single K-pass over A_hi/A_lo/B_hi/B_lo tiles; fp32->bf16 split fused into
// the layer-1 GEMM load phase), two-stream fork retained.
//
//   deg[n]  = 1 + sum_{e: dst[e]==n} ew[e];  dinv = rsqrt(deg)
//   h       = x @ W          (HMMA: a_hi*b_hi + a_lo*b_hi + a_hi*b_lo)
//   out[d]  = dinv[d]*sum_e (w_e*dinv[s_e]) h[s_e] + dinv[d]^2 h[d] + b
// ---------------------------------------------------------------------------

#define MAX_NODES 50000
#define MAX_EDGES 1600000
#define F1 128
#define F2 64
#define K1DIM 256
#define SCAN_CHUNK 256
#define NUM_CHUNKS ((MAX_NODES + SCAN_CHUNK - 1) / SCAN_CHUNK)

__device__ int   g_count [MAX_NODES];
__device__ float g_deg   [MAX_NODES];
__device__ int   g_row   [MAX_NODES + 1];
__device__ int   g_cursor[MAX_NODES];
__device__ int   g_bsum  [NUM_CHUNKS];
__device__ int   g_bpre  [NUM_CHUNKS];
__device__ int2  g_edge  [MAX_EDGES];       // (src, w*dinv[src]) sorted by dst
__device__ float g_dinv  [MAX_NODES];
__device__ float g_h1    [MAX_NODES * F1];
__device__ float g_h2    [MAX_NODES * F2];
__device__ __nv_bfloat16 g_x2hi[MAX_NODES * F1];
__device__ __nv_bfloat16 g_x2lo[MAX_NODES * F1];
__device__ __nv_bfloat16 g_w1hi[F1 * K1DIM];   // W1^T [N=128, K=256]
__device__ __nv_bfloat16 g_w1lo[F1 * K1DIM];
__device__ __nv_bfloat16 g_w2hi[F2 * F1];      // W2^T [N=64, K=128]
__device__ __nv_bfloat16 g_w2lo[F2 * F1];
__device__ int   g_i64;

// ---------------- dtype detect / CSR build --------------------------------
__device__ __forceinline__ int load_idx(const void* ei, long long pos, int i64) {
    if (i64) return (int)((const long long*)ei)[pos];
    return ((const int*)ei)[pos];
}

__global__ void k_detect(const int* __restrict__ ei32) {
    __shared__ int nonzero;
    if (threadIdx.x == 0) nonzero = 0;
    __syncthreads();
    if (ei32[threadIdx.x * 2 + 1] != 0) atomicOr(&nonzero, 1);
    __syncthreads();
    if (threadIdx.x == 0) g_i64 = (nonzero == 0) ? 1 : 0;
}

__global__ void k_zero(int M) {
    int i = blockIdx.x * blockDim.x + threadIdx.x;
    if (i < M) { g_count[i] = 0; g_deg[i] = 1.0f; }
}

__global__ void k_histdeg(const void* __restrict__ ei,
                          const float* __restrict__ ew, int E) {
    int e = blockIdx.x * blockDim.x + threadIdx.x;
    if (e >= E) return;
    int d = load_idx(ei, (long long)E + e, g_i64);
    atomicAdd(&g_count[d], 1);
    atomicAdd(&g_deg[d], ew[e]);
}

__global__ void k_partial(int M) {
    __shared__ int wsum[8];
    int i = blockIdx.x * SCAN_CHUNK + threadIdx.x;
    int lane = threadIdx.x & 31, wid = threadIdx.x >> 5;
    int v = (i < M) ? g_count[i] : 0;
    #pragma unroll
    for (int off = 16; off > 0; off >>= 1)
        v += __shfl_xor_sync(0xffffffffu, v, off);
    if (lane == 0) wsum[wid] = v;
    __syncthreads();
    if (threadIdx.x == 0) {
        int s = 0;
        #pragma unroll
        for (int w = 0; w < 8; w++) s += wsum[w];
        g_bsum[blockIdx.x] = s;
    }
}

__global__ void k_scanb(int NB) {
    __shared__ int wpre[8];
    int tid = threadIdx.x, lane = tid & 31, wid = tid >> 5;
    int v = (tid < NB) ? g_bsum[tid] : 0;
    int inc = v;
    #pragma unroll
    for (int off = 1; off < 32; off <<= 1) {
        int t = __shfl_up_sync(0xffffffffu, inc, off);
        if (lane >= off) inc += t;
    }
    if (lane == 31) wpre[wid] = inc;
    __syncthreads();
    if (wid == 0) {
        int w = (lane < 8) ? wpre[lane] : 0;
        #pragma unroll
        for (int off = 1; off < 8; off <<= 1) {
            int t = __shfl_up_sync(0xffffffffu, w, off);
            if (lane >= off) w += t;
        }
        if (lane < 8) wpre[lane] = w;
    }
    __syncthreads();
    int excl = inc - v + (wid > 0 ? wpre[wid - 1] : 0);
    if (tid < NB) g_bpre[tid] = excl;
}

__global__ void k_write(int M) {
    __shared__ int wpre[8];
    int i = blockIdx.x * SCAN_CHUNK + threadIdx.x;
    int lane = threadIdx.x & 31, wid = threadIdx.x >> 5;
    int c = (i < M) ? g_count[i] : 0;
    int inc = c;
    #pragma unroll
    for (int off = 1; off < 32; off <<= 1) {
        int t = __shfl_up_sync(0xffffffffu, inc, off);
        if (lane >= off) inc += t;
    }
    if (lane == 31) wpre[wid] = inc;
    __syncthreads();
    if (wid == 0) {
        int w = (lane < 8) ? wpre[lane] : 0;
        #pragma unroll
        for (int off = 1; off < 8; off <<= 1) {
            int t = __shfl_up_sync(0xffffffffu, w, off);
            if (lane >= off) w += t;
        }
        if (lane < 8) wpre[lane] = w;
    }
    __syncthreads();
    int excl = inc - c + (wid > 0 ? wpre[wid - 1] : 0) + g_bpre[blockIdx.x];
    if (i < M) {
        g_row[i]    = excl;
        g_cursor[i] = excl;
        g_dinv[i]   = rsqrtf(g_deg[i]);
        if (i == M - 1) g_row[M] = excl + c;
    }
}

__global__ void k_fill(const void* __restrict__ ei,
                       const float* __restrict__ ew, int E) {
    int e = blockIdx.x * blockDim.x + threadIdx.x;
    if (e >= E) return;
    int i64 = g_i64;
    int s = load_idx(ei, e, i64);
    int d = load_idx(ei, (long long)E + e, i64);
    int pos = atomicAdd(&g_cursor[d], 1);
    g_edge[pos] = make_int2(s, __float_as_int(ew[e] * g_dinv[s]));
}

// W [K,N] fp32 -> W^T hi/lo [N,K] bf16
__global__ void k_prepW(const float* __restrict__ W,
                        __nv_bfloat16* __restrict__ Thi,
                        __nv_bfloat16* __restrict__ Tlo, int K, int N) {
    int i = blockIdx.x * blockDim.x + threadIdx.x;
    if (i >= K * N) return;
    int k = i / N, n = i % N;
    float v = W[i];
    __nv_bfloat16 h = __float2bfloat16(v);
    Thi[n * K + k] = h;
    Tlo[n * K + k] = __float2bfloat16(v - __bfloat162float(h));
}

// ---------------- ldmatrix helpers -----------------------------------------
__device__ __forceinline__ uint32_t sm_addr(const void* p) {
    return (uint32_t)__cvta_generic_to_shared(p);
}
__device__ __forceinline__ void ldm_x4(uint32_t* r, uint32_t a) {
    asm volatile("ldmatrix.sync.aligned.m8n8.x4.shared.b16 {%0,%1,%2,%3}, [%4];"
                 : "=r"(r[0]), "=r"(r[1]), "=r"(r[2]), "=r"(r[3]) : "r"(a));
}
__device__ __forceinline__ void ldm_x2(uint32_t* r, uint32_t a) {
    asm volatile("ldmatrix.sync.aligned.m8n8.x2.shared.b16 {%0,%1}, [%2];"
                 : "=r"(r[0]), "=r"(r[1]) : "r"(a));
}
__device__ __forceinline__ void mma16816(float* c, const uint32_t* a, const uint32_t* b) {
    asm volatile(
        "mma.sync.aligned.m16n8k16.row.col.f32.bf16.bf16.f32 "
        "{%0,%1,%2,%3}, {%4,%5,%6,%7}, {%8,%9}, {%0,%1,%2,%3};"
        : "+f"(c[0]), "+f"(c[1]), "+f"(c[2]), "+f"(c[3])
        : "r"(a[0]), "r"(a[1]), "r"(a[2]), "r"(a[3]), "r"(b[0]), "r"(b[1]));
}

// ---------------------------------------------------------------------------
// split GEMM, single K pass: C = A@B^T with A ~ Ah+Al, B ~ Bh+Bl
//   acc += Ah*Bh + Al*Bh + Ah*Bl
// AFP32: A read as fp32 and split in the load phase (layer 1).
// Otherwise A read from pre-split bf16 hi/lo (layer 2).
// BM=128, BN=N, BK=64. 8 warps (4 M x 2 N). Fragments via ldmatrix.
// ---------------------------------------------------------------------------
template<int N, int K, bool AFP32>
__global__ void __launch_bounds__(256, 2) k_gemm_lds(
    const float* __restrict__ Af,
    const __nv_bfloat16* __restrict__ Ahi, const __nv_bfloat16* __restrict__ Alo,
    const __nv_bfloat16* __restrict__ Bhi, const __nv_bfloat16* __restrict__ Blo,
    float* __restrict__ C, int M)
{
    constexpr int BK = 64;
    constexpr int SP = BK + 8;            // 72 bf16 = 144B row stride
    constexpr int NT = N / 16;

    extern __shared__ __nv_bfloat16 sm[];
    __nv_bfloat16* Ah = sm;
    __nv_bfloat16* Al = Ah + 128 * SP;
    __nv_bfloat16* Bh = Al + 128 * SP;
    __nv_bfloat16* Bl = Bh + N * SP;

    const int tid  = threadIdx.x;
    const int wid  = tid >> 5, lane = tid & 31;
    const int wm   = wid & 3,  wn   = wid >> 2;
    const int row0 = blockIdx.x * 128;

    float acc[2][NT][4] = {};

    for (int k0 = 0; k0 < K; k0 += BK) {
        __syncthreads();
        if (AFP32) {
            // A: 128 x 64 fp32 -> hi/lo bf16 in smem. 2048 float4, 8/thread.
            #pragma unroll
            for (int i = tid; i < 128 * 16; i += 256) {
                int m = i >> 4, c4 = i & 15;
                int gm = row0 + m;
                float4 v = make_float4(0.f, 0.f, 0.f, 0.f);
                if (gm < M)
                    v = *reinterpret_cast<const float4*>(Af + (size_t)gm * K + k0 + c4 * 4);
                __nv_bfloat16 h0 = __float2bfloat16(v.x), h1 = __float2bfloat16(v.y);
                __nv_bfloat16 h2 = __float2bfloat16(v.z), h3 = __float2bfloat16(v.w);
                __nv_bfloat162 H0 = {h0, h1}, H1 = {h2, h3};
                __nv_bfloat162 L0 = {__float2bfloat16(v.x - __bfloat162float(h0)),
                                     __float2bfloat16(v.y - __bfloat162float(h1))};
                __nv_bfloat162 L1 = {__float2bfloat16(v.z - __bfloat162float(h2)),
                                     __float2bfloat16(v.w - __bfloat162float(h3))};
                *reinterpret_cast<__nv_bfloat162*>(&Ah[m * SP + c4 * 4])     = H0;
                *reinterpret_cast<__nv_bfloat162*>(&Ah[m * SP + c4 * 4 + 2]) = H1;
                *reinterpret_cast<__nv_bfloat162*>(&Al[m * SP + c4 * 4])     = L0;
                *reinterpret_cast<__nv_bfloat162*>(&Al[m * SP + c4 * 4 + 2]) = L1;
            }
        } else {
            #pragma unroll
            for (int i = tid; i < 128 * 8; i += 256) {
                int m = i >> 3, u = i & 7;
                int gm = row0 + m;
                uint4 vh = make_uint4(0, 0, 0, 0), vl = make_uint4(0, 0, 0, 0);
                if (gm < M) {
                    vh = *reinterpret_cast<const uint4*>(Ahi + (size_t)gm * K + k0 + u * 8);
                    vl = *reinterpret_cast<const uint4*>(Alo + (size_t)gm * K + k0 + u * 8);
                }
                *reinterpret_cast<uint4*>(&Ah[m * SP + u * 8]) = vh;
                *reinterpret_cast<uint4*>(&Al[m * SP + u * 8]) = vl;
            }
        }
        #pragma unroll
        for (int i = tid; i < N * 8; i += 256) {
            int n = i >> 3, u = i & 7;
            uint4 vh = *reinterpret_cast<const uint4*>(Bhi + (size_t)n * K + k0 + u * 8);
            uint4 vl = *reinterpret_cast<const uint4*>(Blo + (size_t)n * K + k0 + u * 8);
            *reinterpret_cast<uint4*>(&Bh[n * SP + u * 8]) = vh;
            *reinterpret_cast<uint4*>(&Bl[n * SP + u * 8]) = vl;
        }
        __syncthreads();

        #pragma unroll
        for (int ks = 0; ks < BK / 16; ks++) {
            uint32_t ah[2][4], al[2][4];
            #pragma unroll
            for (int mt = 0; mt < 2; mt++) {
                int r   = wm * 32 + mt * 16 + (lane & 15);
                int col = ks * 16 + ((lane >> 4) << 3);
                ldm_x4(ah[mt], sm_addr(&Ah[r * SP + col]));
                ldm_x4(al[mt], sm_addr(&Al[r * SP + col]));
            }
            uint32_t bh[NT][2], bl[NT][2];
            #pragma unroll
            for (int nt = 0; nt < NT; nt++) {
                int n   = wn * (N / 2) + nt * 8 + (lane & 7);
                int col = ks * 16 + (((lane >> 3) & 1) << 3);
                ldm_x2(bh[nt], sm_addr(&Bh[n * SP + col]));
                ldm_x2(bl[nt], sm_addr(&Bl[n * SP + col]));
            }
            #pragma unroll
            for (int mt = 0; mt < 2; mt++)
                #pragma unroll
                for (int nt = 0; nt < NT; nt++) {
                    mma16816(acc[mt][nt], ah[mt], bh[nt]);
                    mma16816(acc[mt][nt], al[mt], bh[nt]);
                    mma16816(acc[mt][nt], ah[mt], bl[nt]);
                }
        }
    }

    const int lr = lane >> 2, lc = lane & 3;
    #pragma unroll
    for (int mt = 0; mt < 2; mt++) {
        int r  = row0 + wm * 32 + mt * 16 + lr;
        int r2 = r + 8;
        #pragma unroll
        for (int nt = 0; nt < NT; nt++) {
            int cb = wn * (N / 2) + nt * 8 + lc * 2;
            if (r < M)
                *reinterpret_cast<float2*>(C + (size_t)r  * N + cb) =
                    make_float2(acc[mt][nt][0], acc[mt][nt][1]);
            if (r2 < M)
                *reinterpret_cast<float2*>(C + (size_t)r2 * N + cb) =
                    make_float2(acc[mt][nt][2], acc[mt][nt][3]);
        }
    }
}

// ---------------------------------------------------------------------------
// aggregation: o[d] = act( dinv[d]*sum_e w'_e h[s] + dinv[d]^2 h[d] + bias )
// ---------------------------------------------------------------------------
template<int F, int VEC, bool RELU, bool SPLIT_OUT>
__global__ void k_agg(const float* __restrict__ h,
                      const float* __restrict__ bias,
                      float* __restrict__ out_f32,
                      __nv_bfloat16* __restrict__ out_hi,
                      __nv_bfloat16* __restrict__ out_lo, int M) {
    static_assert(F == 32 * VEC, "lane layout");
    int warp = (blockIdx.x * blockDim.x + threadIdx.x) >> 5;
    int lane = threadIdx.x & 31;
    if (warp >= M) return;

    const int r0 = g_row[warp], r1 = g_row[warp + 1];
    const int nfull = r0 + (((r1 - r0) >> 5) << 5);
    float acc[VEC] = {};

    for (int base = r0; base < nfull; base += 32) {
        int2 rec = g_edge[base + lane];
        #pragma unroll 4
        for (int j = 0; j < 32; j++) {
            int   sj = __shfl_sync(0xffffffffu, rec.x, j);
            float wj = __int_as_float(__shfl_sync(0xffffffffu, rec.y, j));
            const float* p = h + (size_t)sj * F + lane * VEC;
            if (VEC == 4) {
                float4 v = *reinterpret_cast<const float4*>(p);
                acc[0] += v.x * wj; acc[1] += v.y * wj;
                acc[2] += v.z * wj; acc[3] += v.w * wj;
            } else {
                float2 v = *reinterpret_cast<const float2*>(p);
                acc[0] += v.x * wj; acc[1] += v.y * wj;
            }
        }
    }
    {
        int n = r1 - nfull;
        int2 rec = make_int2(0, 0);
        if (lane < n) rec = g_edge[nfull + lane];
        for (int j = 0; j < n; j++) {
            int   sj = __shfl_sync(0xffffffffu, rec.x, j);
            float wj = __int_as_float(__shfl_sync(0xffffffffu, rec.y, j));
            const float* p = h + (size_t)sj * F + lane * VEC;
            if (VEC == 4) {
                float4 v = *reinterpret_cast<const float4*>(p);
                acc[0] += v.x * wj; acc[1] += v.y * wj;
                acc[2] += v.z * wj; acc[3] += v.w * wj;
            } else {
                float2 v = *reinterpret_cast<const float2*>(p);
                acc[0] += v.x * wj; acc[1] += v.y * wj;
            }
        }
    }

    const float* ps = h + (size_t)warp * F + lane * VEC;
    float di  = g_dinv[warp];
    float di2 = di * di;
    float r[VEC];
    #pragma unroll
    for (int k = 0; k < VEC; k++) {
        float o = di * acc[k] + di2 * ps[k] + bias[lane * VEC + k];
        r[k] = (RELU && o < 0.0f) ? 0.0f : o;
    }
    if (SPLIT_OUT) {
        __nv_bfloat16 hi[VEC], lo[VEC];
        #pragma unroll
        for (int k = 0; k < VEC; k++) {
            hi[k] = __float2bfloat16(r[k]);
            lo[k] = __float2bfloat16(r[k] - __bfloat162float(hi[k]));
        }
        __nv_bfloat16* ph = out_hi + (size_t)warp * F + lane * VEC;
        __nv_bfloat16* pl = out_lo + (size_t)warp * F + lane * VEC;
        #pragma unroll
        for (int k = 0; k < VEC; k += 2) {
            *reinterpret_cast<__nv_bfloat162*>(ph + k) = __nv_bfloat162{hi[k], hi[k + 1]};
            *reinterpret_cast<__nv_bfloat162*>(pl + k) = __nv_bfloat162{lo[k], lo[k + 1]};
        }
    } else {
        float* po = out_f32 + (size_t)warp * F + lane * VEC;
        if (VEC == 4) *reinterpret_cast<float4*>(po) = make_float4(r[0], r[1], r[2], r[3]);
        else          *reinterpret_cast<float2*>(po) = make_float2(r[0], r[1]);
    }
}

// ---------------------------------------------------------------------------
extern "C" void kernel_launch(void* const* d_in, const int* in_sizes, int n_in,
                              void* d_out, int out_size) {
    const float* x   = (const float*)d_in[0];
    const void*  ei  = d_in[1];
    const float* ew  = (const float*)d_in[2];
    const float* W1  = (const float*)d_in[3];
    const float* b1  = (const float*)d_in[4];
    const float* W2  = (const float*)d_in[5];
    const float* b2  = (const float*)d_in[6];
    float*       out = (float*)d_out;

    const int N1 = in_sizes[4];            // 128
    const int N2 = in_sizes[6];            // 64
    const int K1 = in_sizes[3] / N1;       // 256
    const int M  = in_sizes[0] / K1;       // 50000
    const int E  = in_sizes[2];            // 1600000
    const int NB = (M + SCAN_CHUNK - 1) / SCAN_CHUNK;

    float *p_h1, *p_h2;
    __nv_bfloat16 *p_x2hi, *p_x2lo, *p_w1hi, *p_w1lo, *p_w2hi, *p_w2lo;
    cudaGetSymbolAddress((void**)&p_h1,   g_h1);
    cudaGetSymbolAddress((void**)&p_h2,   g_h2);
    cudaGetSymbolAddress((void**)&p_x2hi, g_x2hi);
    cudaGetSymbolAddress((void**)&p_x2lo, g_x2lo);
    cudaGetSymbolAddress((void**)&p_w1hi, g_w1hi);
    cudaGetSymbolAddress((void**)&p_w1lo, g_w1lo);
    cudaGetSymbolAddress((void**)&p_w2hi, g_w2hi);
    cudaGetSymbolAddress((void**)&p_w2lo, g_w2lo);

    // dynamic smem: (2*128 + 2*N) * 72 * 2 bytes
    const int SMEM1 = (2 * 128 + 2 * 128) * 72 * 2;   // 73728
    const int SMEM2 = (2 * 128 + 2 * 64)  * 72 * 2;   // 55296
    static bool attrset = false;
    if (!attrset) {
        cudaFuncSetAttribute(k_gemm_lds<128, 256, true>,
                             cudaFuncAttributeMaxDynamicSharedMemorySize, SMEM1);
        cudaFuncSetAttribute(k_gemm_lds<64, 128, false>,
                             cudaFuncAttributeMaxDynamicSharedMemorySize, SMEM2);
        attrset = true;
    }

    // Lazily-created side stream + fork/join events (host resources only).
    static cudaStream_t s2 = nullptr;
    static cudaEvent_t  evFork = nullptr, evJoin = nullptr;
    static bool         inited = false;
    if (!inited) {
        if (cudaStreamCreateWithFlags(&s2, cudaStreamNonBlocking) != cudaSuccess) s2 = nullptr;
        cudaEventCreateWithFlags(&evFork, cudaEventDisableTiming);
        cudaEventCreateWithFlags(&evJoin, cudaEventDisableTiming);
        inited = true;
    }
    cudaStream_t sB = s2 ? s2 : (cudaStream_t)0;
    const bool forked = (s2 != nullptr) && evFork && evJoin;

    // ---- fork ----
    if (forked) {
        cudaEventRecord(evFork, 0);
        cudaStreamWaitEvent(sB, evFork, 0);
    }

    // Stream B: W transpose/split + layer-1 GEMM (x split fused into GEMM)
    k_prepW<<<(K1 * N1 + 255) / 256, 256, 0, sB>>>(W1, p_w1hi, p_w1lo, K1, N1);
    k_prepW<<<(N1 * N2 + 255) / 256, 256, 0, sB>>>(W2, p_w2hi, p_w2lo, N1, N2);
    k_gemm_lds<128, 256, true><<<(M + 127) / 128, 256, SMEM1, sB>>>(
        x, nullptr, nullptr, p_w1hi, p_w1lo, p_h1, M);

    // Stream 0: CSR build
    k_detect <<<1, 256>>>((const int*)ei);
    k_zero   <<<(M + 255) / 256, 256>>>(M);
    k_histdeg<<<(E + 255) / 256, 256>>>(ei, ew, E);
    k_partial<<<NB, SCAN_CHUNK>>>(M);
    k_scanb  <<<1, 256>>>(NB);
    k_write  <<<NB, SCAN_CHUNK>>>(M);
    k_fill   <<<(E + 255) / 256, 256>>>(ei, ew, E);

    // ---- join ----
    if (forked) {
        cudaEventRecord(evJoin, sB);
        cudaStreamWaitEvent(0, evJoin, 0);
    }

    // layer 1 aggregate -> x2 (bf16 hi/lo)
    k_agg<F1, 4, true, true><<<(M * 32 + 255) / 256, 256>>>(p_h1, b1, nullptr, p_x2hi, p_x2lo, M);

    // layer 2: gemm + aggregate -> out
    k_gemm_lds<64, 128, false><<<(M + 127) / 128, 256, SMEM2>>>(
        nullptr, p_x2hi, p_x2lo, p_w2hi, p_w2lo, p_h2, M);
    k_agg<F2, 2, false, false><<<(M * 32 + 255) / 256, 256>>>(p_h2, b2, out, nullptr, nullptr, M);
}

// round 12
// speedup vs baseline: 1.1505x; 1.0084x over previous
#include <cuda_runtime.h>
#include <cuda_bf16.h>
#include <cstdint>

// ---------------------------------------------------------------------------
// TwoLayerGCN on GB300 — round 11: ldmatrix + shared-fragment split GEMM
// (single K-pass over A_hi/A_lo/B_hi/B_lo tiles; fp32->bf16 split fused into
// the layer-1 GEMM load phase), two-stream fork retained.
//
//   deg[n]  = 1 + sum_{e: dst[e]==n} ew[e];  dinv = rsqrt(deg)
//   h       = x @ W          (HMMA: a_hi*b_hi + a_lo*b_hi + a_hi*b_lo)
//   out[d]  = dinv[d]*sum_e (w_e*dinv[s_e]) h[s_e] + dinv[d]^2 h[d] + b
// ---------------------------------------------------------------------------

#define MAX_NODES 50000
#define MAX_EDGES 1600000
#define F1 128
#define F2 64
#define K1DIM 256
#define SCAN_CHUNK 256
#define NUM_CHUNKS ((MAX_NODES + SCAN_CHUNK - 1) / SCAN_CHUNK)

__device__ int   g_count [MAX_NODES];
__device__ float g_deg   [MAX_NODES];
__device__ int   g_row   [MAX_NODES + 1];
__device__ int   g_cursor[MAX_NODES];
__device__ int   g_bsum  [NUM_CHUNKS];
__device__ int   g_bpre  [NUM_CHUNKS];
__device__ int2  g_edge  [MAX_EDGES];       // (src, w*dinv[src]) sorted by dst
__device__ float g_dinv  [MAX_NODES];
__device__ float g_h1    [MAX_NODES * F1];
__device__ float g_h2    [MAX_NODES * F2];
__device__ __nv_bfloat16 g_x2hi[MAX_NODES * F1];
__device__ __nv_bfloat16 g_x2lo[MAX_NODES * F1];
__device__ __nv_bfloat16 g_w1hi[F1 * K1DIM];   // W1^T [N=128, K=256]
__device__ __nv_bfloat16 g_w1lo[F1 * K1DIM];
__device__ __nv_bfloat16 g_w2hi[F2 * F1];      // W2^T [N=64, K=128]
__device__ __nv_bfloat16 g_w2lo[F2 * F1];
__device__ int   g_i64;

// ---------------- dtype detect / CSR build --------------------------------
__device__ __forceinline__ int load_idx(const void* ei, long long pos, int i64) {
    if (i64) return (int)((const long long*)ei)[pos];
    return ((const int*)ei)[pos];
}

__global__ void k_detect(const int* __restrict__ ei32) {
    __shared__ int nonzero;
    if (threadIdx.x == 0) nonzero = 0;
    __syncthreads();
    if (ei32[threadIdx.x * 2 + 1] != 0) atomicOr(&nonzero, 1);
    __syncthreads();
    if (threadIdx.x == 0) g_i64 = (nonzero == 0) ? 1 : 0;
}

__global__ void k_zero(int M) {
    int i = blockIdx.x * blockDim.x + threadIdx.x;
    if (i < M) { g_count[i] = 0; g_deg[i] = 1.0f; }
}

__global__ void k_histdeg(const void* __restrict__ ei,
                          const float* __restrict__ ew, int E) {
    int e = blockIdx.x * blockDim.x + threadIdx.x;
    if (e >= E) return;
    int d = load_idx(ei, (long long)E + e, g_i64);
    atomicAdd(&g_count[d], 1);
    atomicAdd(&g_deg[d], ew[e]);
}

__global__ void k_partial(int M) {
    __shared__ int wsum[8];
    int i = blockIdx.x * SCAN_CHUNK + threadIdx.x;
    int lane = threadIdx.x & 31, wid = threadIdx.x >> 5;
    int v = (i < M) ? g_count[i] : 0;
    #pragma unroll
    for (int off = 16; off > 0; off >>= 1)
        v += __shfl_xor_sync(0xffffffffu, v, off);
    if (lane == 0) wsum[wid] = v;
    __syncthreads();
    if (threadIdx.x == 0) {
        int s = 0;
        #pragma unroll
        for (int w = 0; w < 8; w++) s += wsum[w];
        g_bsum[blockIdx.x] = s;
    }
}

__global__ void k_scanb(int NB) {
    __shared__ int wpre[8];
    int tid = threadIdx.x, lane = tid & 31, wid = tid >> 5;
    int v = (tid < NB) ? g_bsum[tid] : 0;
    int inc = v;
    #pragma unroll
    for (int off = 1; off < 32; off <<= 1) {
        int t = __shfl_up_sync(0xffffffffu, inc, off);
        if (lane >= off) inc += t;
    }
    if (lane == 31) wpre[wid] = inc;
    __syncthreads();
    if (wid == 0) {
        int w = (lane < 8) ? wpre[lane] : 0;
        #pragma unroll
        for (int off = 1; off < 8; off <<= 1) {
            int t = __shfl_up_sync(0xffffffffu, w, off);
            if (lane >= off) w += t;
        }
        if (lane < 8) wpre[lane] = w;
    }
    __syncthreads();
    int excl = inc - v + (wid > 0 ? wpre[wid - 1] : 0);
    if (tid < NB) g_bpre[tid] = excl;
}

__global__ void k_write(int M) {
    __shared__ int wpre[8];
    int i = blockIdx.x * SCAN_CHUNK + threadIdx.x;
    int lane = threadIdx.x & 31, wid = threadIdx.x >> 5;
    int c = (i < M) ? g_count[i] : 0;
    int inc = c;
    #pragma unroll
    for (int off = 1; off < 32; off <<= 1) {
        int t = __shfl_up_sync(0xffffffffu, inc, off);
        if (lane >= off) inc += t;
    }
    if (lane == 31) wpre[wid] = inc;
    __syncthreads();
    if (wid == 0) {
        int w = (lane < 8) ? wpre[lane] : 0;
        #pragma unroll
        for (int off = 1; off < 8; off <<= 1) {
            int t = __shfl_up_sync(0xffffffffu, w, off);
            if (lane >= off) w += t;
        }
        if (lane < 8) wpre[lane] = w;
    }
    __syncthreads();
    int excl = inc - c + (wid > 0 ? wpre[wid - 1] : 0) + g_bpre[blockIdx.x];
    if (i < M) {
        g_row[i]    = excl;
        g_cursor[i] = excl;
        g_dinv[i]   = rsqrtf(g_deg[i]);
        if (i == M - 1) g_row[M] = excl + c;
    }
}

__global__ void k_fill(const void* __restrict__ ei,
                       const float* __restrict__ ew, int E) {
    int e = blockIdx.x * blockDim.x + threadIdx.x;
    if (e >= E) return;
    int i64 = g_i64;
    int s = load_idx(ei, e, i64);
    int d = load_idx(ei, (long long)E + e, i64);
    int pos = atomicAdd(&g_cursor[d], 1);
    g_edge[pos] = make_int2(s, __float_as_int(ew[e] * g_dinv[s]));
}

// W [K,N] fp32 -> W^T hi/lo [N,K] bf16
__global__ void k_prepW(const float* __restrict__ W,
                        __nv_bfloat16* __restrict__ Thi,
                        __nv_bfloat16* __restrict__ Tlo, int K, int N) {
    int i = blockIdx.x * blockDim.x + threadIdx.x;
    if (i >= K * N) return;
    int k = i / N, n = i % N;
    float v = W[i];
    __nv_bfloat16 h = __float2bfloat16(v);
    Thi[n * K + k] = h;
    Tlo[n * K + k] = __float2bfloat16(v - __bfloat162float(h));
}

// ---------------- ldmatrix helpers -----------------------------------------
__device__ __forceinline__ uint32_t sm_addr(const void* p) {
    return (uint32_t)__cvta_generic_to_shared(p);
}
__device__ __forceinline__ void ldm_x4(uint32_t* r, uint32_t a) {
    asm volatile("ldmatrix.sync.aligned.m8n8.x4.shared.b16 {%0,%1,%2,%3}, [%4];"
                 : "=r"(r[0]), "=r"(r[1]), "=r"(r[2]), "=r"(r[3]) : "r"(a));
}
__device__ __forceinline__ void ldm_x2(uint32_t* r, uint32_t a) {
    asm volatile("ldmatrix.sync.aligned.m8n8.x2.shared.b16 {%0,%1}, [%2];"
                 : "=r"(r[0]), "=r"(r[1]) : "r"(a));
}
__device__ __forceinline__ void mma16816(float* c, const uint32_t* a, const uint32_t* b) {
    asm volatile(
        "mma.sync.aligned.m16n8k16.row.col.f32.bf16.bf16.f32 "
        "{%0,%1,%2,%3}, {%4,%5,%6,%7}, {%8,%9}, {%0,%1,%2,%3};"
        : "+f"(c[0]), "+f"(c[1]), "+f"(c[2]), "+f"(c[3])
        : "r"(a[0]), "r"(a[1]), "r"(a[2]), "r"(a[3]), "r"(b[0]), "r"(b[1]));
}

// ---------------------------------------------------------------------------
// split GEMM, single K pass: C = A@B^T with A ~ Ah+Al, B ~ Bh+Bl
//   acc += Ah*Bh + Al*Bh + Ah*Bl
// AFP32: A read as fp32 and split in the load phase (layer 1).
// Otherwise A read from pre-split bf16 hi/lo (layer 2).
// BM=128, BN=N, BK=64. 8 warps (4 M x 2 N). Fragments via ldmatrix.
// ---------------------------------------------------------------------------
template<int N, int K, bool AFP32>
__global__ void __launch_bounds__(256, 2) k_gemm_lds(
    const float* __restrict__ Af,
    const __nv_bfloat16* __restrict__ Ahi, const __nv_bfloat16* __restrict__ Alo,
    const __nv_bfloat16* __restrict__ Bhi, const __nv_bfloat16* __restrict__ Blo,
    float* __restrict__ C, int M)
{
    constexpr int BK = 64;
    constexpr int SP = BK + 8;            // 72 bf16 = 144B row stride
    constexpr int NT = N / 16;

    extern __shared__ __nv_bfloat16 sm[];
    __nv_bfloat16* Ah = sm;
    __nv_bfloat16* Al = Ah + 128 * SP;
    __nv_bfloat16* Bh = Al + 128 * SP;
    __nv_bfloat16* Bl = Bh + N * SP;

    const int tid  = threadIdx.x;
    const int wid  = tid >> 5, lane = tid & 31;
    const int wm   = wid & 3,  wn   = wid >> 2;
    const int row0 = blockIdx.x * 128;

    float acc[2][NT][4] = {};

    for (int k0 = 0; k0 < K; k0 += BK) {
        __syncthreads();
        if (AFP32) {
            // A: 128 x 64 fp32 -> hi/lo bf16 in smem. 2048 float4, 8/thread.
            #pragma unroll
            for (int i = tid; i < 128 * 16; i += 256) {
                int m = i >> 4, c4 = i & 15;
                int gm = row0 + m;
                float4 v = make_float4(0.f, 0.f, 0.f, 0.f);
                if (gm < M)
                    v = *reinterpret_cast<const float4*>(Af + (size_t)gm * K + k0 + c4 * 4);
                __nv_bfloat16 h0 = __float2bfloat16(v.x), h1 = __float2bfloat16(v.y);
                __nv_bfloat16 h2 = __float2bfloat16(v.z), h3 = __float2bfloat16(v.w);
                __nv_bfloat162 H0 = {h0, h1}, H1 = {h2, h3};
                __nv_bfloat162 L0 = {__float2bfloat16(v.x - __bfloat162float(h0)),
                                     __float2bfloat16(v.y - __bfloat162float(h1))};
                __nv_bfloat162 L1 = {__float2bfloat16(v.z - __bfloat162float(h2)),
                                     __float2bfloat16(v.w - __bfloat162float(h3))};
                *reinterpret_cast<__nv_bfloat162*>(&Ah[m * SP + c4 * 4])     = H0;
                *reinterpret_cast<__nv_bfloat162*>(&Ah[m * SP + c4 * 4 + 2]) = H1;
                *reinterpret_cast<__nv_bfloat162*>(&Al[m * SP + c4 * 4])     = L0;
                *reinterpret_cast<__nv_bfloat162*>(&Al[m * SP + c4 * 4 + 2]) = L1;
            }
        } else {
            #pragma unroll
            for (int i = tid; i < 128 * 8; i += 256) {
                int m = i >> 3, u = i & 7;
                int gm = row0 + m;
                uint4 vh = make_uint4(0, 0, 0, 0), vl = make_uint4(0, 0, 0, 0);
                if (gm < M) {
                    vh = *reinterpret_cast<const uint4*>(Ahi + (size_t)gm * K + k0 + u * 8);
                    vl = *reinterpret_cast<const uint4*>(Alo + (size_t)gm * K + k0 + u * 8);
                }
                *reinterpret_cast<uint4*>(&Ah[m * SP + u * 8]) = vh;
                *reinterpret_cast<uint4*>(&Al[m * SP + u * 8]) = vl;
            }
        }
        #pragma unroll
        for (int i = tid; i < N * 8; i += 256) {
            int n = i >> 3, u = i & 7;
            uint4 vh = *reinterpret_cast<const uint4*>(Bhi + (size_t)n * K + k0 + u * 8);
            uint4 vl = *reinterpret_cast<const uint4*>(Blo + (size_t)n * K + k0 + u * 8);
            *reinterpret_cast<uint4*>(&Bh[n * SP + u * 8]) = vh;
            *reinterpret_cast<uint4*>(&Bl[n * SP + u * 8]) = vl;
        }
        __syncthreads();

        #pragma unroll
        for (int ks = 0; ks < BK / 16; ks++) {
            uint32_t ah[2][4], al[2][4];
            #pragma unroll
            for (int mt = 0; mt < 2; mt++) {
                int r   = wm * 32 + mt * 16 + (lane & 15);
                int col = ks * 16 + ((lane >> 4) << 3);
                ldm_x4(ah[mt], sm_addr(&Ah[r * SP + col]));
                ldm_x4(al[mt], sm_addr(&Al[r * SP + col]));
            }
            uint32_t bh[NT][2], bl[NT][2];
            #pragma unroll
            for (int nt = 0; nt < NT; nt++) {
                int n   = wn * (N / 2) + nt * 8 + (lane & 7);
                int col = ks * 16 + (((lane >> 3) & 1) << 3);
                ldm_x2(bh[nt], sm_addr(&Bh[n * SP + col]));
                ldm_x2(bl[nt], sm_addr(&Bl[n * SP + col]));
            }
            #pragma unroll
            for (int mt = 0; mt < 2; mt++)
                #pragma unroll
                for (int nt = 0; nt < NT; nt++) {
                    mma16816(acc[mt][nt], ah[mt], bh[nt]);
                    mma16816(acc[mt][nt], al[mt], bh[nt]);
                    mma16816(acc[mt][nt], ah[mt], bl[nt]);
                }
        }
    }

    const int lr = lane >> 2, lc = lane & 3;
    #pragma unroll
    for (int mt = 0; mt < 2; mt++) {
        int r  = row0 + wm * 32 + mt * 16 + lr;
        int r2 = r + 8;
        #pragma unroll
        for (int nt = 0; nt < NT; nt++) {
            int cb = wn * (N / 2) + nt * 8 + lc * 2;
            if (r < M)
                *reinterpret_cast<float2*>(C + (size_t)r  * N + cb) =
                    make_float2(acc[mt][nt][0], acc[mt][nt][1]);
            if (r2 < M)
                *reinterpret_cast<float2*>(C + (size_t)r2 * N + cb) =
                    make_float2(acc[mt][nt][2], acc[mt][nt][3]);
        }
    }
}

// ---------------------------------------------------------------------------
// aggregation: o[d] = act( dinv[d]*sum_e w'_e h[s] + dinv[d]^2 h[d] + bias )
// ---------------------------------------------------------------------------
template<int F, int VEC, bool RELU, bool SPLIT_OUT>
__global__ void k_agg(const float* __restrict__ h,
                      const float* __restrict__ bias,
                      float* __restrict__ out_f32,
                      __nv_bfloat16* __restrict__ out_hi,
                      __nv_bfloat16* __restrict__ out_lo, int M) {
    static_assert(F == 32 * VEC, "lane layout");
    int warp = (blockIdx.x * blockDim.x + threadIdx.x) >> 5;
    int lane = threadIdx.x & 31;
    if (warp >= M) return;

    const int r0 = g_row[warp], r1 = g_row[warp + 1];
    const int nfull = r0 + (((r1 - r0) >> 5) << 5);
    float acc[VEC] = {};

    for (int base = r0; base < nfull; base += 32) {
        int2 rec = g_edge[base + lane];
        #pragma unroll 4
        for (int j = 0; j < 32; j++) {
            int   sj = __shfl_sync(0xffffffffu, rec.x, j);
            float wj = __int_as_float(__shfl_sync(0xffffffffu, rec.y, j));
            const float* p = h + (size_t)sj * F + lane * VEC;
            if (VEC == 4) {
                float4 v = *reinterpret_cast<const float4*>(p);
                acc[0] += v.x * wj; acc[1] += v.y * wj;
                acc[2] += v.z * wj; acc[3] += v.w * wj;
            } else {
                float2 v = *reinterpret_cast<const float2*>(p);
                acc[0] += v.x * wj; acc[1] += v.y * wj;
            }
        }
    }
    {
        int n = r1 - nfull;
        int2 rec = make_int2(0, 0);
        if (lane < n) rec = g_edge[nfull + lane];
        for (int j = 0; j < n; j++) {
            int   sj = __shfl_sync(0xffffffffu, rec.x, j);
            float wj = __int_as_float(__shfl_sync(0xffffffffu, rec.y, j));
            const float* p = h + (size_t)sj * F + lane * VEC;
            if (VEC == 4) {
                float4 v = *reinterpret_cast<const float4*>(p);
                acc[0] += v.x * wj; acc[1] += v.y * wj;
                acc[2] += v.z * wj; acc[3] += v.w * wj;
            } else {
                float2 v = *reinterpret_cast<const float2*>(p);
                acc[0] += v.x * wj; acc[1] += v.y * wj;
            }
        }
    }

    const float* ps = h + (size_t)warp * F + lane * VEC;
    float di  = g_dinv[warp];
    float di2 = di * di;
    float r[VEC];
    #pragma unroll
    for (int k = 0; k < VEC; k++) {
        float o = di * acc[k] + di2 * ps[k] + bias[lane * VEC + k];
        r[k] = (RELU && o < 0.0f) ? 0.0f : o;
    }
    if (SPLIT_OUT) {
        __nv_bfloat16 hi[VEC], lo[VEC];
        #pragma unroll
        for (int k = 0; k < VEC; k++) {
            hi[k] = __float2bfloat16(r[k]);
            lo[k] = __float2bfloat16(r[k] - __bfloat162float(hi[k]));
        }
        __nv_bfloat16* ph = out_hi + (size_t)warp * F + lane * VEC;
        __nv_bfloat16* pl = out_lo + (size_t)warp * F + lane * VEC;
        #pragma unroll
        for (int k = 0; k < VEC; k += 2) {
            *reinterpret_cast<__nv_bfloat162*>(ph + k) = __nv_bfloat162{hi[k], hi[k + 1]};
            *reinterpret_cast<__nv_bfloat162*>(pl + k) = __nv_bfloat162{lo[k], lo[k + 1]};
        }
    } else {
        float* po = out_f32 + (size_t)warp * F + lane * VEC;
        if (VEC == 4) *reinterpret_cast<float4*>(po) = make_float4(r[0], r[1], r[2], r[3]);
        else          *reinterpret_cast<float2*>(po) = make_float2(r[0], r[1]);
    }
}

// ---------------------------------------------------------------------------
extern "C" void kernel_launch(void* const* d_in, const int* in_sizes, int n_in,
                              void* d_out, int out_size) {
    const float* x   = (const float*)d_in[0];
    const void*  ei  = d_in[1];
    const float* ew  = (const float*)d_in[2];
    const float* W1  = (const float*)d_in[3];
    const float* b1  = (const float*)d_in[4];
    const float* W2  = (const float*)d_in[5];
    const float* b2  = (const float*)d_in[6];
    float*       out = (float*)d_out;

    const int N1 = in_sizes[4];            // 128
    const int N2 = in_sizes[6];            // 64
    const int K1 = in_sizes[3] / N1;       // 256
    const int M  = in_sizes[0] / K1;       // 50000
    const int E  = in_sizes[2];            // 1600000
    const int NB = (M + SCAN_CHUNK - 1) / SCAN_CHUNK;

    float *p_h1, *p_h2;
    __nv_bfloat16 *p_x2hi, *p_x2lo, *p_w1hi, *p_w1lo, *p_w2hi, *p_w2lo;
    cudaGetSymbolAddress((void**)&p_h1,   g_h1);
    cudaGetSymbolAddress((void**)&p_h2,   g_h2);
    cudaGetSymbolAddress((void**)&p_x2hi, g_x2hi);
    cudaGetSymbolAddress((void**)&p_x2lo, g_x2lo);
    cudaGetSymbolAddress((void**)&p_w1hi, g_w1hi);
    cudaGetSymbolAddress((void**)&p_w1lo, g_w1lo);
    cudaGetSymbolAddress((void**)&p_w2hi, g_w2hi);
    cudaGetSymbolAddress((void**)&p_w2lo, g_w2lo);

    // dynamic smem: (2*128 + 2*N) * 72 * 2 bytes
    const int SMEM1 = (2 * 128 + 2 * 128) * 72 * 2;   // 73728
    const int SMEM2 = (2 * 128 + 2 * 64)  * 72 * 2;   // 55296
    static bool attrset = false;
    if (!attrset) {
        cudaFuncSetAttribute(k_gemm_lds<128, 256, true>,
                             cudaFuncAttributeMaxDynamicSharedMemorySize, SMEM1);
        cudaFuncSetAttribute(k_gemm_lds<64, 128, false>,
                             cudaFuncAttributeMaxDynamicSharedMemorySize, SMEM2);
        attrset = true;
    }

    // Lazily-created side stream + fork/join events (host resources only).
    static cudaStream_t s2 = nullptr;
    static cudaEvent_t  evFork = nullptr, evJoin = nullptr;
    static bool         inited = false;
    if (!inited) {
        if (cudaStreamCreateWithFlags(&s2, cudaStreamNonBlocking) != cudaSuccess) s2 = nullptr;
        cudaEventCreateWithFlags(&evFork, cudaEventDisableTiming);
        cudaEventCreateWithFlags(&evJoin, cudaEventDisableTiming);
        inited = true;
    }
    cudaStream_t sB = s2 ? s2 : (cudaStream_t)0;
    const bool forked = (s2 != nullptr) && evFork && evJoin;

    // ---- fork ----
    if (forked) {
        cudaEventRecord(evFork, 0);
        cudaStreamWaitEvent(sB, evFork, 0);
    }

    // Stream B: W transpose/split + layer-1 GEMM (x split fused into GEMM)
    k_prepW<<<(K1 * N1 + 255) / 256, 256, 0, sB>>>(W1, p_w1hi, p_w1lo, K1, N1);
    k_prepW<<<(N1 * N2 + 255) / 256, 256, 0, sB>>>(W2, p_w2hi, p_w2lo, N1, N2);
    k_gemm_lds<128, 256, true><<<(M + 127) / 128, 256, SMEM1, sB>>>(
        x, nullptr, nullptr, p_w1hi, p_w1lo, p_h1, M);

    // Stream 0: CSR build
    k_detect <<<1, 256>>>((const int*)ei);
    k_zero   <<<(M + 255) / 256, 256>>>(M);
    k_histdeg<<<(E + 255) / 256, 256>>>(ei, ew, E);
    k_partial<<<NB, SCAN_CHUNK>>>(M);
    k_scanb  <<<1, 256>>>(NB);
    k_write  <<<NB, SCAN_CHUNK>>>(M);
    k_fill   <<<(E + 255) / 256, 256>>>(ei, ew, E);

    // ---- join ----
    if (forked) {
        cudaEventRecord(evJoin, sB);
        cudaStreamWaitEvent(0, evJoin, 0);
    }

    // layer 1 aggregate -> x2 (bf16 hi/lo)
    k_agg<F1, 4, true, true><<<(M * 32 + 255) / 256, 256>>>(p_h1, b1, nullptr, p_x2hi, p_x2lo, M);

    // layer 2: gemm + aggregate -> out
    k_gemm_lds<64, 128, false><<<(M + 127) / 128, 256, SMEM2>>>(
        nullptr, p_x2hi, p_x2lo, p_w2hi, p_w2lo, p_h2, M);
    k_agg<F2, 2, false, false><<<(M * 32 + 255) / 256, 256>>>(p_h2, b2, out, nullptr, nullptr, M);
}